// round 7
// baseline (speedup 1.0000x reference)
#include <cuda_runtime.h>
#include <cstdint>

#define B_ 1024
#define T_ 256
#define D_ 64
#define H_ 128
#define RR 6            // rows per CTA in phase B
#define NCTA ((B_ + RR - 1) / RR)   // 171

// Precomputed x-projections (pre-activation, bias included).
__device__ float g_xg[(size_t)B_ * T_ * 256];   // gate: r cols 0..127, u cols 128..255
__device__ float g_xc[(size_t)B_ * T_ * 128];   // candidate
__device__ int   g_perm[B_];                    // rows sorted by len desc

// ---- packed f32x2 helpers ----
__device__ __forceinline__ unsigned long long pack2(float lo, float hi) {
    unsigned long long r;
    asm("mov.b64 %0, {%1, %2};" : "=l"(r) : "f"(lo), "f"(hi));
    return r;
}
__device__ __forceinline__ void fma2(unsigned long long& acc,
                                     unsigned long long a,
                                     unsigned long long b) {
    asm("fma.rn.f32x2 %0, %1, %2, %0;" : "+l"(acc) : "l"(a), "l"(b));
}
__device__ __forceinline__ float sum2(unsigned long long a) {
    float lo, hi;
    asm("mov.b64 {%0, %1}, %2;" : "=f"(lo), "=f"(hi) : "l"(a));
    return lo + hi;
}
__device__ __forceinline__ float sigmoidf(float s) { return 1.f / (1.f + __expf(-s)); }
__device__ __forceinline__ float tanh_safe(float s) {
    const float sc = fminf(fmaxf(s, -15.f), 15.f);
    const float e  = __expf(2.f * sc);
    return (e - 1.f) / (e + 1.f);
}

// named-barrier producer/consumer sync (384 = all threads in CTA)
#define BSYNC(id)   asm volatile("bar.sync %0, 384;"   :: "r"(id) : "memory")
#define BARRIVE(id) asm volatile("bar.arrive %0, 384;" :: "r"(id) : "memory")

// ============================================================================
// Sort rows by seq_len descending (counting sort, one CTA).
// ============================================================================
__global__ void sort_rows(const int* __restrict__ seq_lens) {
    __shared__ int base[T_ + 1];
    const int tid = threadIdx.x;          // 1024 threads
    if (tid <= T_) base[tid] = 0;
    __syncthreads();
    const int len = seq_lens[tid];
    atomicAdd(&base[len], 1);
    __syncthreads();
    if (tid == 0) {                        // descending prefix
        int acc = 0;
        for (int l = T_; l >= 0; l--) { int c = base[l]; base[l] = acc; acc += c; }
    }
    __syncthreads();
    const int pos = atomicAdd(&base[len], 1);
    g_perm[pos] = tid;
}

// ============================================================================
// Phase A: time-parallel x-projections. Weights in regs, x via LDS.128.
// ============================================================================
__global__ __launch_bounds__(384)
void gru_phaseA(const int* __restrict__ item_his,
                const int* __restrict__ seq_lens,
                const float* __restrict__ emb,
                const float* __restrict__ Wg,
                const float* __restrict__ bg,
                const float* __restrict__ Wc,
                const float* __restrict__ bc)
{
    const int b  = blockIdx.y;
    const int t0 = blockIdx.x * 64;
    const int len = seq_lens[b];
    if (t0 >= len) return;
    const int nt = min(64, len - t0);
    const int tid = threadIdx.x;

    __shared__ int idx_sh[64];
    __shared__ __align__(16) float x_sh[64 * 64];

    unsigned long long wp[32];
    float bias;
    if (tid < 256) {
        bias = bg[tid];
#pragma unroll
        for (int i = 0; i < 32; i++)
            wp[i] = pack2(Wg[(2 * i) * 256 + tid], Wg[(2 * i + 1) * 256 + tid]);
    } else {
        const int c = tid - 256;
        bias = bc[c];
#pragma unroll
        for (int i = 0; i < 32; i++)
            wp[i] = pack2(Wc[(2 * i) * 128 + c], Wc[(2 * i + 1) * 128 + c]);
    }

    if (tid < nt) idx_sh[tid] = item_his[b * T_ + t0 + tid];
    __syncthreads();

    {   // coalesced gather: nt embedding rows of 256B each
        const float4* e4 = (const float4*)emb;
        float4* x4 = (float4*)x_sh;
        for (int i = tid; i < nt * 16; i += 384) {
            const int r = i >> 4, q = i & 15;
            x4[r * 16 + q] = e4[(size_t)idx_sh[r] * 16 + q];
        }
    }
    __syncthreads();

    const ulonglong2* x2 = (const ulonglong2*)x_sh;
    for (int r = 0; r < nt; r += 2) {
        const bool two = (r + 1 < nt);
        unsigned long long a0 = 0ULL, a1 = 0ULL, b0 = 0ULL, b1 = 0ULL;
#pragma unroll
        for (int i = 0; i < 16; i++) {
            ulonglong2 xx = x2[r * 16 + i];
            fma2(a0, xx.x, wp[2 * i]);
            fma2(a1, xx.y, wp[2 * i + 1]);
            if (two) {
                ulonglong2 yy = x2[(r + 1) * 16 + i];
                fma2(b0, yy.x, wp[2 * i]);
                fma2(b1, yy.y, wp[2 * i + 1]);
            }
        }
        const float acc0 = sum2(a0) + sum2(a1) + bias;
        const size_t p0 = (size_t)b * T_ + t0 + r;
        if (tid < 256) __stcs(&g_xg[p0 * 256 + tid], acc0);
        else           __stcs(&g_xc[p0 * 128 + (tid - 256)], acc0);
        if (two) {
            const float acc1 = sum2(b0) + sum2(b1) + bias;
            if (tid < 256) __stcs(&g_xg[(p0 + 1) * 256 + tid], acc1);
            else           __stcs(&g_xc[(p0 + 1) * 128 + (tid - 256)], acc1);
        }
    }
}

// ============================================================================
// Phase B: decoupled producer/consumer recurrence, 6 sorted rows per CTA.
//   A = rows {0,1,2}, B = rows {3,4,5}.
//   gate (256 thr): sync(1) G_A(t) arrive(3) | sync(2) G_B(t) arrive(4)
//   cand (128 thr): sync(3) C_A(t) arrive(1) | sync(4) C_B(t) arrive(2)
//   Unconditional 3-row dots (6 acc chains), guarded writes.
// ============================================================================
__device__ __forceinline__ void dot3(const unsigned long long* __restrict__ wp,
                                     const float* __restrict__ v0,
                                     const float* __restrict__ v1,
                                     const float* __restrict__ v2,
                                     float* __restrict__ s)
{
    const ulonglong2* p0 = (const ulonglong2*)v0;
    const ulonglong2* p1 = (const ulonglong2*)v1;
    const ulonglong2* p2 = (const ulonglong2*)v2;
    unsigned long long a00 = 0ULL, a01 = 0ULL, a10 = 0ULL, a11 = 0ULL,
                       a20 = 0ULL, a21 = 0ULL;
#pragma unroll
    for (int kk = 0; kk < 32; kk++) {
        const unsigned long long w0 = wp[2 * kk], w1 = wp[2 * kk + 1];
        ulonglong2 x0 = p0[kk];
        fma2(a00, x0.x, w0); fma2(a01, x0.y, w1);
        ulonglong2 x1 = p1[kk];
        fma2(a10, x1.x, w0); fma2(a11, x1.y, w1);
        ulonglong2 x2 = p2[kk];
        fma2(a20, x2.x, w0); fma2(a21, x2.y, w1);
    }
    s[0] = sum2(a00) + sum2(a01);
    s[1] = sum2(a10) + sum2(a11);
    s[2] = sum2(a20) + sum2(a21);
}

__global__ __launch_bounds__(384, 1)
void gru_phaseB(const int* __restrict__ seq_lens,
                const float* __restrict__ Wg,
                const float* __restrict__ Wc,
                float* __restrict__ out)
{
    __shared__ __align__(16) float h[RR][128];
    __shared__ __align__(16) float rh[RR][128];
    __shared__ float uu[RR][128];

    const int tid = threadIdx.x;
    const int cta = blockIdx.x;
    const int g0  = cta * RR;
    const int RC  = min(RR, B_ - g0);      // real rows in this CTA

    int len[RR];
    int off[RR];                            // element offset into x array (32-bit)
    const bool isGate = tid < 256;
    const int  j      = isGate ? tid : tid - 256;
    const int  S      = isGate ? 256 : 128;
#pragma unroll
    for (int r = 0; r < RR; r++) {
        const int gi = g0 + r;
        if (gi < B_) {
            const int b = g_perm[gi];
            len[r] = seq_lens[b];
            off[r] = b * (T_ * S) + j;
        } else { len[r] = 0; off[r] = j; }
    }
    const int tmax = len[0];                // sorted desc within group

    for (int i = tid; i < RR * 128; i += 384) ((float*)h)[i] = 0.f;
    __syncthreads();

    if (tmax > 0) {
        const float* xbase = isGate ? g_xg : g_xc;

        unsigned long long wp[64];
        if (isGate) {
#pragma unroll
            for (int i = 0; i < 64; i++)
                wp[i] = pack2(Wg[(64 + 2 * i) * 256 + j], Wg[(64 + 2 * i + 1) * 256 + j]);
        } else {
#pragma unroll
            for (int i = 0; i < 64; i++)
                wp[i] = pack2(Wc[(64 + 2 * i) * 128 + j], Wc[(64 + 2 * i + 1) * 128 + j]);
        }

        float q[RR], qn[RR];
#pragma unroll
        for (int r = 0; r < RR; r++)
            q[r] = (0 < len[r]) ? __ldcs(&xbase[off[r]]) : 0.f;

        // cand pre-arms the h-ready barriers (h zeroed + synced above)
        if (!isGate) { BARRIVE(1); BARRIVE(2); }

        for (int t = 0; t < tmax; t++) {
            // depth-1 prefetch for step t+1
#pragma unroll
            for (int r = 0; r < RR; r++)
                qn[r] = (t + 1 < len[r]) ? __ldcs(&xbase[off[r] + S]) : 0.f;

            if (isGate) {
                // ---- G_A(t): rows 0..2 ----
                BSYNC(1);
                {
                    float s[3]; dot3(wp, h[0], h[1], h[2], s);
#pragma unroll
                    for (int r = 0; r < 3; r++)
                        if (t < len[r]) {
                            const float g = sigmoidf(s[r] + q[r]);
                            if (j < 128) rh[r][j] = g * h[r][j];
                            else         uu[r][j - 128] = g;
                        }
                }
                BARRIVE(3);
                // ---- G_B(t): rows 3..5 ----
                BSYNC(2);
                if (t < len[3]) {
                    float s[3]; dot3(wp, h[3], h[4], h[5], s);
#pragma unroll
                    for (int r = 3; r < 6; r++)
                        if (t < len[r]) {
                            const float g = sigmoidf(s[r - 3] + q[r]);
                            if (j < 128) rh[r][j] = g * h[r][j];
                            else         uu[r][j - 128] = g;
                        }
                }
                BARRIVE(4);
            } else {
                // ---- C_A(t): rows 0..2 ----
                BSYNC(3);
                {
                    float s[3]; dot3(wp, rh[0], rh[1], rh[2], s);
#pragma unroll
                    for (int r = 0; r < 3; r++)
                        if (t < len[r]) {
                            const float c = tanh_safe(s[r] + q[r]);
                            const float u = uu[r][j];
                            h[r][j] = u * h[r][j] + (1.f - u) * c;
                        }
                }
                if (t + 1 < tmax) BARRIVE(1);
                // ---- C_B(t): rows 3..5 ----
                BSYNC(4);
                if (t < len[3]) {
                    float s[3]; dot3(wp, rh[3], rh[4], rh[5], s);
#pragma unroll
                    for (int r = 3; r < 6; r++)
                        if (t < len[r]) {
                            const float c = tanh_safe(s[r - 3] + q[r]);
                            const float u = uu[r][j];
                            h[r][j] = u * h[r][j] + (1.f - u) * c;
                        }
                }
                if (t + 1 < tmax) BARRIVE(2);
            }

#pragma unroll
            for (int r = 0; r < RR; r++) { q[r] = qn[r]; off[r] += S; }
        }
        __syncthreads();
    }

    for (int i = tid; i < RC * 128; i += 384) {
        const int r = i >> 7;
        out[g_perm[g0 + r] * 128 + (i & 127)] = h[r][i & 127];
    }
}

// ============================================================================
extern "C" void kernel_launch(void* const* d_in, const int* in_sizes, int n_in,
                              void* d_out, int out_size)
{
    const int*   item_his = (const int*)d_in[0];
    const int*   seq_lens = (const int*)d_in[1];
    const float* emb      = (const float*)d_in[2];
    const float* Wg       = (const float*)d_in[3];
    const float* bg       = (const float*)d_in[4];
    const float* Wc       = (const float*)d_in[5];
    const float* bc       = (const float*)d_in[6];
    float* out = (float*)d_out;

    sort_rows<<<1, B_>>>(seq_lens);
    dim3 gA(T_ / 64, B_);   // (4, 1024)
    gru_phaseA<<<gA, 384>>>(item_his, seq_lens, emb, Wg, bg, Wc, bc);
    gru_phaseB<<<NCTA, 384>>>(seq_lens, Wg, Wc, out);
}